// round 11
// baseline (speedup 1.0000x reference)
#include <cuda_runtime.h>
#include <cuda_fp16.h>
#include <cstdint>

// Problem constants
#define Tt    1024
#define Bb    8
#define Ee    1024
#define Hh    16
#define Dh    64
#define QKVF  3072           // 3*E
#define MROWS 8192           // T*B

// Scratch (device globals — no runtime allocation allowed)
__device__ __half g_xh  [(size_t)MROWS * Ee];    // query, fp16
__device__ __half g_w1h [(size_t)QKVF * Ee];     // qkv_w, fp16
__device__ __half g_w2h [(size_t)Ee * Ee];       // out_w, fp16
__device__ __half g_qkvh[(size_t)MROWS * QKVF];  // qkv proj out (Q pre-scaled), fp16
__device__ __half g_atth[(size_t)MROWS * Ee];    // attention out, fp16
__device__ int    g_ctr1;                        // GEMM1 tile counter
__device__ int    g_ctr2;                        // GEMM2 tile counter

// ---------------------------------------------------------------------------
// Helpers
// ---------------------------------------------------------------------------
__device__ __forceinline__ uint32_t packh2(float lo, float hi) {
    __half2 h = __floats2half2_rn(lo, hi);
    return *reinterpret_cast<uint32_t*>(&h);
}

__device__ __forceinline__ void mma16(float* c,
                                      uint32_t a0, uint32_t a1, uint32_t a2, uint32_t a3,
                                      uint32_t b0, uint32_t b1) {
    asm volatile("mma.sync.aligned.m16n8k16.row.col.f32.f16.f16.f32 "
                 "{%0,%1,%2,%3}, {%4,%5,%6,%7}, {%8,%9}, {%0,%1,%2,%3};"
                 : "+f"(c[0]), "+f"(c[1]), "+f"(c[2]), "+f"(c[3])
                 : "r"(a0), "r"(a1), "r"(a2), "r"(a3), "r"(b0), "r"(b1));
}

__device__ __forceinline__ void ldsm4(uint32_t& r0, uint32_t& r1, uint32_t& r2, uint32_t& r3,
                                      uint32_t addr) {
    asm volatile("ldmatrix.sync.aligned.m8n8.x4.shared.b16 {%0,%1,%2,%3}, [%4];"
                 : "=r"(r0), "=r"(r1), "=r"(r2), "=r"(r3) : "r"(addr));
}

__device__ __forceinline__ void ldsm4t(uint32_t& r0, uint32_t& r1, uint32_t& r2, uint32_t& r3,
                                       uint32_t addr) {
    asm volatile("ldmatrix.sync.aligned.m8n8.x4.trans.shared.b16 {%0,%1,%2,%3}, [%4];"
                 : "=r"(r0), "=r"(r1), "=r"(r2), "=r"(r3) : "r"(addr));
}

// ---------------------------------------------------------------------------
// Fused prepass: fp32->fp16 for query/qkv_w/out_w, and reset tile counters.
// ---------------------------------------------------------------------------
#define NQ4  (MROWS * Ee / 4)
#define NW14 (QKVF * Ee / 4)
#define NW24 (Ee * Ee / 4)

__global__ void prepass(const float4* __restrict__ q,  const float4* __restrict__ w1,
                        const float4* __restrict__ w2,
                        uint2* __restrict__ xh, uint2* __restrict__ w1h,
                        uint2* __restrict__ w2h)
{
    int i = blockIdx.x * blockDim.x + threadIdx.x;
    if (i == 0) { g_ctr1 = 0; g_ctr2 = 0; }
    float4 v; uint2* dst;
    if (i < NQ4)                  { v = q[i];                dst = &xh[i]; }
    else if (i < NQ4 + NW14)      { v = w1[i - NQ4];         dst = &w1h[i - NQ4]; }
    else if (i < NQ4 + NW14 + NW24) { v = w2[i - NQ4 - NW14]; dst = &w2h[i - NQ4 - NW14]; }
    else return;
    uint2 o;
    o.x = packh2(v.x, v.y);
    o.y = packh2(v.z, v.w);
    *dst = o;
}

// ---------------------------------------------------------------------------
// Persistent fp16 tensor-core GEMM (NT): C[M,N] = A[M,K]*B[N,K]^T, (acc+bias)*scale
// CTA tile 128x128, 4 warps (2m x 2n), warp tile 64x64, BK=32, 4-stage cp.async.
// Persistent CTAs pop tiles from a global counter; the pipeline runs
// CONTINUOUSLY across tile boundaries (stage = global commit ordinal & 3).
// Next tile id is popped 4 chunks early into smem (one barrier between
// write and read). Epilogue overlaps next tile's in-flight prefetches.
// ---------------------------------------------------------------------------
#define BM   128
#define BN   128
#define BKH  32
#define ABY  (BM * 64)          // 8192
#define BBY  (BN * 64)          // 8192
#define STG  (ABY + BBY)        // 16384
#define GSM  (4 * STG + 128)    // stages + control words

__global__ void __launch_bounds__(128, 2) gemm_f16(
    const __half* __restrict__ Ah, const __half* __restrict__ Bh,
    const float* __restrict__ bias, __half* __restrict__ Ch, float* __restrict__ Cf,
    int M, int N, int K, int qscale, int* __restrict__ ctr, int grid_n, int ntiles)
{
    extern __shared__ char smem[];
    const uint32_t sb = (uint32_t)__cvta_generic_to_shared(smem);
    int* tq = (int*)(smem + 4 * STG);
    const int tid  = threadIdx.x;
    const int lane = tid & 31;
    const int warp = tid >> 5;
    const int wm = warp & 1;
    const int wn = warp >> 1;
    const int nk = K / BKH;

    // Pop first tile
    if (tid == 0) tq[0] = atomicAdd(ctr, 1);
    __syncthreads();
    int cur = tq[0];
    if (cur >= ntiles) return;
    int m0 = (cur / grid_n) * BM;
    int n0 = (cur % grid_n) * BN;

    auto load_stage = [&](int s, int mm0, int nn0, int c) {
        const uint32_t base = sb + s * STG;
        const int k0 = c * BKH;
        #pragma unroll
        for (int i = 0; i < 8; i++) {
            int q = tid + i * 128;
            uint32_t dst;
            const __half* src;
            if (q < 512) {                   // A: 128 rows x 4 chunks
                int r = q >> 2, ch = q & 3;
                src = Ah + (size_t)(mm0 + r) * K + k0 + ch * 8;
                dst = base + r * 64 + ((ch ^ ((r >> 1) & 3)) << 4);
            } else {                         // B: 128 rows x 4 chunks
                int q2 = q - 512;
                int r = q2 >> 2, ch = q2 & 3;
                src = Bh + (size_t)(nn0 + r) * K + k0 + ch * 8;
                dst = base + ABY + r * 64 + ((ch ^ ((r >> 1) & 3)) << 4);
            }
            asm volatile("cp.async.cg.shared.global [%0], [%1], 16;" :: "r"(dst), "l"(src));
        }
        asm volatile("cp.async.commit_group;" ::: "memory");
    };

    int commits = 0, consumed = 0;
    #pragma unroll
    for (int c = 0; c < 3; c++) { load_stage(c, m0, n0, c); commits++; }

    const int a_rl = ((lane >> 3) & 1) * 8 + (lane & 7);
    const int a_ck = lane >> 4;
    const int b_rl = ((lane >> 4) & 1) * 8 + (lane & 7);
    const int b_ck = (lane >> 3) & 1;

    // Hoisted fragment byte offsets within a stage (tile-independent)
    uint32_t aoff[2][4], boff[2][4];
    #pragma unroll
    for (int ks = 0; ks < 2; ks++) {
        #pragma unroll
        for (int mt = 0; mt < 4; mt++) {
            int ar = wm * 64 + mt * 16 + a_rl;
            int ch = (2 * ks + a_ck) ^ ((ar >> 1) & 3);
            aoff[ks][mt] = ar * 64 + (ch << 4);
        }
        #pragma unroll
        for (int p = 0; p < 4; p++) {
            int br = wn * 64 + p * 16 + b_rl;
            int ch = (2 * ks + b_ck) ^ ((br >> 1) & 3);
            boff[ks][p] = ABY + br * 64 + (ch << 4);
        }
    }

    const int g = lane >> 2, t = lane & 3;

    while (true) {
        float acc[4][8][4];
        #pragma unroll
        for (int mt = 0; mt < 4; mt++)
            #pragma unroll
            for (int nt = 0; nt < 8; nt++)
                #pragma unroll
                for (int i = 0; i < 4; i++) acc[mt][nt][i] = 0.0f;

        int next = ntiles, nm0 = 0, nn0 = 0;

        for (int c = 0; c < nk; c++) {
            // Exact wait: group for chunk 'consumed' done when pending <= ahead
            int ahead = commits - consumed - 1;
            if (ahead >= 2)      asm volatile("cp.async.wait_group 2;" ::: "memory");
            else if (ahead == 1) asm volatile("cp.async.wait_group 1;" ::: "memory");
            else                 asm volatile("cp.async.wait_group 0;" ::: "memory");
            __syncthreads();

            // Pop next tile id 4 chunks before it's needed (read next iter)
            if (c == nk - 4 && tid == 0) tq[1] = atomicAdd(ctr, 1);

            if (c + 3 < nk) {
                load_stage(commits & 3, m0, n0, c + 3);
                commits++;
            } else {
                if (c == nk - 3) {
                    next = tq[1];   // written at c==nk-4; barrier separates
                    if (next < ntiles) {
                        nm0 = (next / grid_n) * BM;
                        nn0 = (next % grid_n) * BN;
                    }
                }
                if (next < ntiles) {
                    load_stage(commits & 3, nm0, nn0, c + 3 - nk);
                    commits++;
                }
            }

            const uint32_t base = sb + (consumed & 3) * STG;
            #pragma unroll
            for (int ks = 0; ks < 2; ks++) {
                uint32_t af[4][4], bf[8][2];
                #pragma unroll
                for (int mt = 0; mt < 4; mt++)
                    ldsm4(af[mt][0], af[mt][1], af[mt][2], af[mt][3], base + aoff[ks][mt]);
                #pragma unroll
                for (int p = 0; p < 4; p++) {
                    uint32_t r0, r1, r2, r3;
                    ldsm4(r0, r1, r2, r3, base + boff[ks][p]);
                    bf[2 * p][0] = r0;     bf[2 * p][1] = r1;
                    bf[2 * p + 1][0] = r2; bf[2 * p + 1][1] = r3;
                }
                #pragma unroll
                for (int mt = 0; mt < 4; mt++)
                    #pragma unroll
                    for (int nt = 0; nt < 8; nt++)
                        mma16(acc[mt][nt], af[mt][0], af[mt][1], af[mt][2], af[mt][3],
                              bf[nt][0], bf[nt][1]);
            }
            consumed++;
        }

        // Epilogue (register->gmem; overlaps next tile's in-flight prefetches)
        const float scale = (qscale && n0 < Ee) ? 0.125f : 1.0f;
        #pragma unroll
        for (int mt = 0; mt < 4; mt++) {
            const int r0 = m0 + wm * 64 + mt * 16 + g;
            #pragma unroll
            for (int nt = 0; nt < 8; nt++) {
                const int col = n0 + wn * 64 + nt * 8 + 2 * t;
                const float b0 = bias[col], b1 = bias[col + 1];
                float v00 = (acc[mt][nt][0] + b0) * scale;
                float v01 = (acc[mt][nt][1] + b1) * scale;
                float v10 = (acc[mt][nt][2] + b0) * scale;
                float v11 = (acc[mt][nt][3] + b1) * scale;
                if (Ch) {
                    *(uint32_t*)&Ch[(size_t)r0 * N + col]       = packh2(v00, v01);
                    *(uint32_t*)&Ch[(size_t)(r0 + 8) * N + col] = packh2(v10, v11);
                } else {
                    *(float2*)&Cf[(size_t)r0 * N + col]       = make_float2(v00, v01);
                    *(float2*)&Cf[(size_t)(r0 + 8) * N + col] = make_float2(v10, v11);
                }
            }
        }

        if (next >= ntiles) break;
        cur = next; m0 = nm0; n0 = nn0;
    }
}

// ---------------------------------------------------------------------------
// Flash attention, fp16 tensor cores, causal — proven R7 version
// (64-row q-tile, 4 warps, reversed qt order, double-buffered K/V).
// ---------------------------------------------------------------------------
#define FST 16384   // per-stage bytes: K 8KB + V 8KB

__global__ void __launch_bounds__(128) flash_f16()
{
    __shared__ __align__(128) char fsm[2 * FST];
    const uint32_t sb = (uint32_t)__cvta_generic_to_shared(fsm);

    const int tid  = threadIdx.x;
    const int lane = tid & 31;
    const int g    = lane >> 2;
    const int t    = lane & 3;
    const int w    = tid >> 5;
    const int qt   = gridDim.x - 1 - blockIdx.x;   // heavy tiles first
    const int bh   = blockIdx.y;
    const int b    = bh >> 4;
    const int h    = bh & 15;
    const int q0   = qt * 64;

    // Q fragments (Q already scaled by 0.125 in GEMM1 epilogue)
    uint32_t qa[4][4];
    {
        const __half* qlo = g_qkvh + ((size_t)(q0 + w * 16 + g) * Bb + b) * QKVF + h * Dh;
        const __half* qhi = qlo + (size_t)8 * Bb * QKVF;
        #pragma unroll
        for (int ks = 0; ks < 4; ks++) {
            qa[ks][0] = *(const uint32_t*)(qlo + ks * 16 + 2 * t);
            qa[ks][1] = *(const uint32_t*)(qhi + ks * 16 + 2 * t);
            qa[ks][2] = *(const uint32_t*)(qlo + ks * 16 + 8 + 2 * t);
            qa[ks][3] = *(const uint32_t*)(qhi + ks * 16 + 8 + 2 * t);
        }
    }

    auto load_kv = [&](int st, int kt) {
        const uint32_t base = sb + st * FST;
        const int k0 = kt * 64;
        #pragma unroll
        for (int i = 0; i < 8; i++) {
            int q = tid + i * 128;
            int off, s, c;
            uint32_t dstb;
            if (q < 512) { s = q >> 3; c = q & 7; off = Ee;     dstb = base; }
            else { int q2 = q - 512; s = q2 >> 3; c = q2 & 7; off = 2 * Ee; dstb = base + 8192; }
            const __half* src = g_qkvh + ((size_t)(k0 + s) * Bb + b) * QKVF + off + h * Dh + c * 8;
            uint32_t dst = dstb + s * 128 + ((c ^ (s & 7)) << 4);
            asm volatile("cp.async.cg.shared.global [%0], [%1], 16;" :: "r"(dst), "l"(src));
        }
        asm volatile("cp.async.commit_group;" ::: "memory");
    };

    load_kv(0, 0);

    float o[8][4];
    #pragma unroll
    for (int nt = 0; nt < 8; nt++)
        #pragma unroll
        for (int i = 0; i < 4; i++) o[nt][i] = 0.0f;
    float m0v = -1e30f, m1v = -1e30f, l0 = 0.0f, l1 = 0.0f;

    const int krl = ((lane >> 4) & 1) * 8 + (lane & 7);
    const int kck = (lane >> 3) & 1;
    const int vrl = ((lane >> 3) & 1) * 8 + (lane & 7);
    const int vck = lane >> 4;

    for (int kt = 0; kt <= qt; kt++) {
        asm volatile("cp.async.wait_group 0;" ::: "memory");
        __syncthreads();
        if (kt < qt) load_kv((kt + 1) & 1, kt + 1);

        const uint32_t Kb = sb + (kt & 1) * FST;
        const uint32_t Vb = Kb + 8192;

        // S = Q K^T
        float sv[8][4];
        #pragma unroll
        for (int nt = 0; nt < 8; nt++)
            #pragma unroll
            for (int i = 0; i < 4; i++) sv[nt][i] = 0.0f;

        #pragma unroll
        for (int ks = 0; ks < 4; ks++) {
            #pragma unroll
            for (int p = 0; p < 4; p++) {
                int n = p * 16 + krl;
                int ch = (2 * ks + kck) ^ (n & 7);
                uint32_t r0, r1, r2, r3;
                ldsm4(r0, r1, r2, r3, Kb + n * 128 + (ch << 4));
                mma16(sv[2 * p],     qa[ks][0], qa[ks][1], qa[ks][2], qa[ks][3], r0, r1);
                mma16(sv[2 * p + 1], qa[ks][0], qa[ks][1], qa[ks][2], qa[ks][3], r2, r3);
            }
        }

        // Causal mask (diagonal tile only)
        if (kt == qt) {
            const int r_lo = w * 16 + g, r_hi = r_lo + 8;
            #pragma unroll
            for (int nt = 0; nt < 8; nt++) {
                const int c0 = nt * 8 + 2 * t, c1 = c0 + 1;
                if (c0 > r_lo) sv[nt][0] = -1e30f;
                if (c1 > r_lo) sv[nt][1] = -1e30f;
                if (c0 > r_hi) sv[nt][2] = -1e30f;
                if (c1 > r_hi) sv[nt][3] = -1e30f;
            }
        }

        // Online softmax
        float mx0 = -1e30f, mx1 = -1e30f;
        #pragma unroll
        for (int nt = 0; nt < 8; nt++) {
            mx0 = fmaxf(mx0, fmaxf(sv[nt][0], sv[nt][1]));
            mx1 = fmaxf(mx1, fmaxf(sv[nt][2], sv[nt][3]));
        }
        mx0 = fmaxf(mx0, __shfl_xor_sync(0xffffffffu, mx0, 1));
        mx0 = fmaxf(mx0, __shfl_xor_sync(0xffffffffu, mx0, 2));
        mx1 = fmaxf(mx1, __shfl_xor_sync(0xffffffffu, mx1, 1));
        mx1 = fmaxf(mx1, __shfl_xor_sync(0xffffffffu, mx1, 2));

        const float mn0 = fmaxf(m0v, mx0), mn1 = fmaxf(m1v, mx1);
        const float al0 = __expf(m0v - mn0), al1 = __expf(m1v - mn1);
        m0v = mn0; m1v = mn1;

        float sum0 = 0.0f, sum1 = 0.0f;
        #pragma unroll
        for (int nt = 0; nt < 8; nt++) {
            sv[nt][0] = __expf(sv[nt][0] - mn0); sum0 += sv[nt][0];
            sv[nt][1] = __expf(sv[nt][1] - mn0); sum0 += sv[nt][1];
            sv[nt][2] = __expf(sv[nt][2] - mn1); sum1 += sv[nt][2];
            sv[nt][3] = __expf(sv[nt][3] - mn1); sum1 += sv[nt][3];
        }
        sum0 += __shfl_xor_sync(0xffffffffu, sum0, 1);
        sum0 += __shfl_xor_sync(0xffffffffu, sum0, 2);
        sum1 += __shfl_xor_sync(0xffffffffu, sum1, 1);
        sum1 += __shfl_xor_sync(0xffffffffu, sum1, 2);
        l0 = l0 * al0 + sum0;
        l1 = l1 * al1 + sum1;

        #pragma unroll
        for (int nt = 0; nt < 8; nt++) {
            o[nt][0] *= al0; o[nt][1] *= al0;
            o[nt][2] *= al1; o[nt][3] *= al1;
        }

        // O += P V  (P register-resident, packed to fp16)
        #pragma unroll
        for (int ks = 0; ks < 4; ks++) {
            const uint32_t p0 = packh2(sv[2 * ks][0],     sv[2 * ks][1]);
            const uint32_t p1 = packh2(sv[2 * ks][2],     sv[2 * ks][3]);
            const uint32_t p2 = packh2(sv[2 * ks + 1][0], sv[2 * ks + 1][1]);
            const uint32_t p3 = packh2(sv[2 * ks + 1][2], sv[2 * ks + 1][3]);
            #pragma unroll
            for (int p = 0; p < 4; p++) {
                int srow = ks * 16 + vrl;
                int ch = (2 * p + vck) ^ (srow & 7);
                uint32_t r0, r1, r2, r3;
                ldsm4t(r0, r1, r2, r3, Vb + srow * 128 + (ch << 4));
                mma16(o[2 * p],     p0, p1, p2, p3, r0, r1);
                mma16(o[2 * p + 1], p0, p1, p2, p3, r2, r3);
            }
        }
    }

    // Epilogue: normalize, write fp16 [T,B,E]
    const float inv0 = 1.0f / l0, inv1 = 1.0f / l1;
    __half* dlo = g_atth + ((size_t)(q0 + w * 16 + g) * Bb + b) * Ee + h * Dh;
    __half* dhi = dlo + (size_t)8 * Bb * Ee;
    #pragma unroll
    for (int nt = 0; nt < 8; nt++) {
        const int c = nt * 8 + 2 * t;
        *(uint32_t*)&dlo[c] = packh2(o[nt][0] * inv0, o[nt][1] * inv0);
        *(uint32_t*)&dhi[c] = packh2(o[nt][2] * inv1, o[nt][3] * inv1);
    }
}

// ---------------------------------------------------------------------------
// Launch
// ---------------------------------------------------------------------------
extern "C" void kernel_launch(void* const* d_in, const int* in_sizes, int n_in,
                              void* d_out, int out_size)
{
    const float* query = (const float*)d_in[0];
    const float* qkv_w = (const float*)d_in[1];
    const float* qkv_b = (const float*)d_in[2];
    const float* out_w = (const float*)d_in[3];
    const float* out_b = (const float*)d_in[4];
    float* out = (float*)d_out;

    void *p_xh = nullptr, *p_w1h = nullptr, *p_w2h = nullptr,
         *p_qkvh = nullptr, *p_atth = nullptr, *p_c1 = nullptr, *p_c2 = nullptr;
    cudaGetSymbolAddress(&p_xh,   g_xh);
    cudaGetSymbolAddress(&p_w1h,  g_w1h);
    cudaGetSymbolAddress(&p_w2h,  g_w2h);
    cudaGetSymbolAddress(&p_qkvh, g_qkvh);
    cudaGetSymbolAddress(&p_atth, g_atth);
    cudaGetSymbolAddress(&p_c1,   g_ctr1);
    cudaGetSymbolAddress(&p_c2,   g_ctr2);

    cudaFuncSetAttribute(gemm_f16, cudaFuncAttributeMaxDynamicSharedMemorySize, GSM);

    int nsm = 148;
    cudaDeviceGetAttribute(&nsm, cudaDevAttrMultiProcessorCount, 0);
    const int pgrid = 2 * nsm;

    // 0) fused prepass: fp32->fp16 conversions + counter resets
    const int ntot4 = NQ4 + NW14 + NW24;
    prepass<<<(ntot4 + 255) / 256, 256>>>(
        (const float4*)query, (const float4*)qkv_w, (const float4*)out_w,
        (uint2*)p_xh, (uint2*)p_w1h, (uint2*)p_w2h);

    // 1) QKV projection -> fp16, Q block scaled by 0.125 (persistent)
    gemm_f16<<<pgrid, 128, GSM>>>(
        (const __half*)p_xh, (const __half*)p_w1h, qkv_b,
        (__half*)p_qkvh, nullptr, MROWS, QKVF, Ee, 1,
        (int*)p_c1, QKVF / BN, (MROWS / BM) * (QKVF / BN));

    // 2) Causal flash attention per (query-tile, b*H+h)
    flash_f16<<<dim3(Tt / 64, Bb * Hh), 128>>>();

    // 3) Output projection -> fp32 final output (persistent)
    gemm_f16<<<pgrid, 128, GSM>>>(
        (const __half*)p_atth, (const __half*)p_w2h, out_b,
        nullptr, out, MROWS, Ee, Ee, 0,
        (int*)p_c2, Ee / BN, (MROWS / BM) * (Ee / BN));
}

// round 13
// speedup vs baseline: 1.0482x; 1.0482x over previous
#include <cuda_runtime.h>
#include <cuda_fp16.h>
#include <cstdint>

// Problem constants
#define Tt    1024
#define Bb    8
#define Ee    1024
#define Hh    16
#define Dh    64
#define QKVF  3072           // 3*E
#define MROWS 8192           // T*B

// Scratch (device globals — no runtime allocation allowed)
__device__ __half g_xh  [(size_t)MROWS * Ee];    // query, fp16
__device__ __half g_w1h [(size_t)QKVF * Ee];     // qkv_w, fp16
__device__ __half g_w2h [(size_t)Ee * Ee];       // out_w, fp16
__device__ __half g_qkvh[(size_t)MROWS * QKVF];  // qkv proj out (Q pre-scaled), fp16
__device__ __half g_atth[(size_t)MROWS * Ee];    // attention out, fp16
__device__ int    g_cnt[16];                     // per-qt flash completion counters

// ---------------------------------------------------------------------------
// Helpers
// ---------------------------------------------------------------------------
__device__ __forceinline__ uint32_t packh2(float lo, float hi) {
    __half2 h = __floats2half2_rn(lo, hi);
    return *reinterpret_cast<uint32_t*>(&h);
}

__device__ __forceinline__ void mma16(float* c,
                                      uint32_t a0, uint32_t a1, uint32_t a2, uint32_t a3,
                                      uint32_t b0, uint32_t b1) {
    asm volatile("mma.sync.aligned.m16n8k16.row.col.f32.f16.f16.f32 "
                 "{%0,%1,%2,%3}, {%4,%5,%6,%7}, {%8,%9}, {%0,%1,%2,%3};"
                 : "+f"(c[0]), "+f"(c[1]), "+f"(c[2]), "+f"(c[3])
                 : "r"(a0), "r"(a1), "r"(a2), "r"(a3), "r"(b0), "r"(b1));
}

__device__ __forceinline__ void ldsm4(uint32_t& r0, uint32_t& r1, uint32_t& r2, uint32_t& r3,
                                      uint32_t addr) {
    asm volatile("ldmatrix.sync.aligned.m8n8.x4.shared.b16 {%0,%1,%2,%3}, [%4];"
                 : "=r"(r0), "=r"(r1), "=r"(r2), "=r"(r3) : "r"(addr));
}

__device__ __forceinline__ void ldsm4t(uint32_t& r0, uint32_t& r1, uint32_t& r2, uint32_t& r3,
                                       uint32_t addr) {
    asm volatile("ldmatrix.sync.aligned.m8n8.x4.trans.shared.b16 {%0,%1,%2,%3}, [%4];"
                 : "=r"(r0), "=r"(r1), "=r"(r2), "=r"(r3) : "r"(addr));
}

// ---------------------------------------------------------------------------
// Fused prepass: fp32->fp16 for query/qkv_w/out_w, reset counters.
// ---------------------------------------------------------------------------
#define NQ4  (MROWS * Ee / 4)
#define NW14 (QKVF * Ee / 4)
#define NW24 (Ee * Ee / 4)

__global__ void prepass(const float4* __restrict__ q,  const float4* __restrict__ w1,
                        const float4* __restrict__ w2,
                        uint2* __restrict__ xh, uint2* __restrict__ w1h,
                        uint2* __restrict__ w2h)
{
    int i = blockIdx.x * blockDim.x + threadIdx.x;
    if (i < 16) g_cnt[i] = 0;
    float4 v; uint2* dst;
    if (i < NQ4)                    { v = q[i];                 dst = &xh[i]; }
    else if (i < NQ4 + NW14)        { v = w1[i - NQ4];          dst = &w1h[i - NQ4]; }
    else if (i < NQ4 + NW14 + NW24) { v = w2[i - NQ4 - NW14];   dst = &w2h[i - NQ4 - NW14]; }
    else return;
    uint2 o;
    o.x = packh2(v.x, v.y);
    o.y = packh2(v.z, v.w);
    *dst = o;
}

// ---------------------------------------------------------------------------
// fp16 tensor-core GEMM (NT) — proven R7 config (used for GEMM1).
// CTA 128x128, 4 warps (2m x 2n), warp tile 64x64, BK=32, 4-stage cp.async.
// ---------------------------------------------------------------------------
#define BM   128
#define BN   128
#define BKH  32
#define NSG  4
#define ABY  (BM * 64)          // 8192
#define BBY  (BN * 64)          // 8192
#define STG  (ABY + BBY)        // 16384
#define GSM  (NSG * STG)        // 65536

__global__ void __launch_bounds__(128, 2) gemm_f16(
    const __half* __restrict__ Ah, const __half* __restrict__ Bh,
    const float* __restrict__ bias, __half* __restrict__ Ch,
    int M, int N, int K, int qscale)
{
    extern __shared__ char smem[];
    const uint32_t sb = (uint32_t)__cvta_generic_to_shared(smem);
    const int tid  = threadIdx.x;
    const int lane = tid & 31;
    const int warp = tid >> 5;
    const int wm = warp & 1;
    const int wn = warp >> 1;
    const int m0 = blockIdx.y * BM;
    const int n0 = blockIdx.x * BN;

    float acc[4][8][4];
    #pragma unroll
    for (int mt = 0; mt < 4; mt++)
        #pragma unroll
        for (int nt = 0; nt < 8; nt++)
            #pragma unroll
            for (int i = 0; i < 4; i++) acc[mt][nt][i] = 0.0f;

    auto load_stage = [&](int s, int c) {
        const uint32_t base = sb + s * STG;
        const int k0 = c * BKH;
        #pragma unroll
        for (int i = 0; i < 8; i++) {
            int q = tid + i * 128;
            uint32_t dst;
            const __half* src;
            if (q < 512) {
                int r = q >> 2, ch = q & 3;
                src = Ah + (size_t)(m0 + r) * K + k0 + ch * 8;
                dst = base + r * 64 + ((ch ^ ((r >> 1) & 3)) << 4);
            } else {
                int q2 = q - 512;
                int r = q2 >> 2, ch = q2 & 3;
                src = Bh + (size_t)(n0 + r) * K + k0 + ch * 8;
                dst = base + ABY + r * 64 + ((ch ^ ((r >> 1) & 3)) << 4);
            }
            asm volatile("cp.async.cg.shared.global [%0], [%1], 16;" :: "r"(dst), "l"(src));
        }
        asm volatile("cp.async.commit_group;" ::: "memory");
    };

    const int nk = K / BKH;
    load_stage(0, 0);
    load_stage(1, 1);
    load_stage(2, 2);

    const int a_rl = ((lane >> 3) & 1) * 8 + (lane & 7);
    const int a_ck = lane >> 4;
    const int b_rl = ((lane >> 4) & 1) * 8 + (lane & 7);
    const int b_ck = (lane >> 3) & 1;

    uint32_t aoff[2][4], boff[2][4];
    #pragma unroll
    for (int ks = 0; ks < 2; ks++) {
        #pragma unroll
        for (int mt = 0; mt < 4; mt++) {
            int ar = wm * 64 + mt * 16 + a_rl;
            int ch = (2 * ks + a_ck) ^ ((ar >> 1) & 3);
            aoff[ks][mt] = ar * 64 + (ch << 4);
        }
        #pragma unroll
        for (int p = 0; p < 4; p++) {
            int br = wn * 64 + p * 16 + b_rl;
            int ch = (2 * ks + b_ck) ^ ((br >> 1) & 3);
            boff[ks][p] = ABY + br * 64 + (ch << 4);
        }
    }

    for (int c = 0; c < nk; c++) {
        const int s = c & (NSG - 1);
        if (c < nk - 1) asm volatile("cp.async.wait_group 2;" ::: "memory");
        else            asm volatile("cp.async.wait_group 0;" ::: "memory");
        __syncthreads();
        if (c + NSG - 1 < nk) load_stage((c + NSG - 1) & (NSG - 1), c + NSG - 1);

        const uint32_t base = sb + s * STG;
        #pragma unroll
        for (int ks = 0; ks < 2; ks++) {
            uint32_t af[4][4], bf[8][2];
            #pragma unroll
            for (int mt = 0; mt < 4; mt++)
                ldsm4(af[mt][0], af[mt][1], af[mt][2], af[mt][3], base + aoff[ks][mt]);
            #pragma unroll
            for (int p = 0; p < 4; p++) {
                uint32_t r0, r1, r2, r3;
                ldsm4(r0, r1, r2, r3, base + boff[ks][p]);
                bf[2 * p][0] = r0;     bf[2 * p][1] = r1;
                bf[2 * p + 1][0] = r2; bf[2 * p + 1][1] = r3;
            }
            #pragma unroll
            for (int mt = 0; mt < 4; mt++)
                #pragma unroll
                for (int nt = 0; nt < 8; nt++)
                    mma16(acc[mt][nt], af[mt][0], af[mt][1], af[mt][2], af[mt][3],
                          bf[nt][0], bf[nt][1]);
        }
    }

    const float scale = (qscale && n0 < Ee) ? 0.125f : 1.0f;
    const int g = lane >> 2, t = lane & 3;
    #pragma unroll
    for (int mt = 0; mt < 4; mt++) {
        const int r0 = m0 + wm * 64 + mt * 16 + g;
        #pragma unroll
        for (int nt = 0; nt < 8; nt++) {
            const int col = n0 + wn * 64 + nt * 8 + 2 * t;
            const float b0 = bias[col], b1 = bias[col + 1];
            *(uint32_t*)&Ch[(size_t)r0 * N + col] =
                packh2((acc[mt][nt][0] + b0) * scale, (acc[mt][nt][1] + b1) * scale);
            *(uint32_t*)&Ch[(size_t)(r0 + 8) * N + col] =
                packh2((acc[mt][nt][2] + b0) * scale, (acc[mt][nt][3] + b1) * scale);
        }
    }
}

// ---------------------------------------------------------------------------
// FUSED flash + GEMM2 kernel.
// bids [0, 2048): flash blocks (proven R7 double-buffered inner loop),
//   natural qt order (qt = bid>>7); bump g_cnt[qt] on completion (release).
// bids [2048, 2560): GEMM2 tiles (early tokens first); acquire-spin on
//   g_cnt[qt(m_tile)]==128, then run the R7 GEMM loop -> out (fp32, +out_b).
// Deadlock-free: CTAs dispatch in bid order; all flash bids precede GEMM2.
// ---------------------------------------------------------------------------
#define NFLASH 2048
#define FSTG   16384   // per-stage: K 8KB + V 8KB

__global__ void __launch_bounds__(128) flash_gemm2(
    const float* __restrict__ out_b, float* __restrict__ out)
{
    extern __shared__ char smem[];
    const uint32_t sb = (uint32_t)__cvta_generic_to_shared(smem);
    const int tid  = threadIdx.x;
    const int lane = tid & 31;
    const int g    = lane >> 2;
    const int t    = lane & 3;
    const int w    = tid >> 5;
    const int bid  = blockIdx.x;

    if (bid < NFLASH) {
        // ================= FLASH path (R7 double-buffer) =================
        const int qt = bid >> 7;        // natural order: light first
        const int bh = bid & 127;
        const int b  = bh >> 4;
        const int h  = bh & 15;
        const int q0 = qt * 64;

        uint32_t qa[4][4];
        {
            const __half* qlo = g_qkvh + ((size_t)(q0 + w * 16 + g) * Bb + b) * QKVF + h * Dh;
            const __half* qhi = qlo + (size_t)8 * Bb * QKVF;
            #pragma unroll
            for (int ks = 0; ks < 4; ks++) {
                qa[ks][0] = *(const uint32_t*)(qlo + ks * 16 + 2 * t);
                qa[ks][1] = *(const uint32_t*)(qhi + ks * 16 + 2 * t);
                qa[ks][2] = *(const uint32_t*)(qlo + ks * 16 + 8 + 2 * t);
                qa[ks][3] = *(const uint32_t*)(qhi + ks * 16 + 8 + 2 * t);
            }
        }

        auto load_kv = [&](int st, int kt) {
            const uint32_t base = sb + st * FSTG;
            const int k0 = kt * 64;
            #pragma unroll
            for (int i = 0; i < 8; i++) {
                int q = tid + i * 128;
                int off, s, c;
                uint32_t dstb;
                if (q < 512) { s = q >> 3; c = q & 7; off = Ee;     dstb = base; }
                else { int q2 = q - 512; s = q2 >> 3; c = q2 & 7; off = 2 * Ee; dstb = base + 8192; }
                const __half* src = g_qkvh + ((size_t)(k0 + s) * Bb + b) * QKVF + off + h * Dh + c * 8;
                uint32_t dst = dstb + s * 128 + ((c ^ (s & 7)) << 4);
                asm volatile("cp.async.cg.shared.global [%0], [%1], 16;" :: "r"(dst), "l"(src));
            }
            asm volatile("cp.async.commit_group;" ::: "memory");
        };

        load_kv(0, 0);

        float o[8][4];
        #pragma unroll
        for (int nt = 0; nt < 8; nt++)
            #pragma unroll
            for (int i = 0; i < 4; i++) o[nt][i] = 0.0f;
        float m0v = -1e30f, m1v = -1e30f, l0 = 0.0f, l1 = 0.0f;

        const int krl = ((lane >> 4) & 1) * 8 + (lane & 7);
        const int kck = (lane >> 3) & 1;
        const int vrl = ((lane >> 3) & 1) * 8 + (lane & 7);
        const int vck = lane >> 4;

        for (int kt = 0; kt <= qt; kt++) {
            asm volatile("cp.async.wait_group 0;" ::: "memory");
            __syncthreads();
            if (kt < qt) load_kv((kt + 1) & 1, kt + 1);

            const uint32_t Kb = sb + (kt & 1) * FSTG;
            const uint32_t Vb = Kb + 8192;

            float sv[8][4];
            #pragma unroll
            for (int nt = 0; nt < 8; nt++)
                #pragma unroll
                for (int i = 0; i < 4; i++) sv[nt][i] = 0.0f;

            #pragma unroll
            for (int ks = 0; ks < 4; ks++) {
                #pragma unroll
                for (int p = 0; p < 4; p++) {
                    int n = p * 16 + krl;
                    int ch = (2 * ks + kck) ^ (n & 7);
                    uint32_t r0, r1, r2, r3;
                    ldsm4(r0, r1, r2, r3, Kb + n * 128 + (ch << 4));
                    mma16(sv[2 * p],     qa[ks][0], qa[ks][1], qa[ks][2], qa[ks][3], r0, r1);
                    mma16(sv[2 * p + 1], qa[ks][0], qa[ks][1], qa[ks][2], qa[ks][3], r2, r3);
                }
            }

            if (kt == qt) {
                const int r_lo = w * 16 + g, r_hi = r_lo + 8;
                #pragma unroll
                for (int nt = 0; nt < 8; nt++) {
                    const int c0 = nt * 8 + 2 * t, c1 = c0 + 1;
                    if (c0 > r_lo) sv[nt][0] = -1e30f;
                    if (c1 > r_lo) sv[nt][1] = -1e30f;
                    if (c0 > r_hi) sv[nt][2] = -1e30f;
                    if (c1 > r_hi) sv[nt][3] = -1e30f;
                }
            }

            float mx0 = -1e30f, mx1 = -1e30f;
            #pragma unroll
            for (int nt = 0; nt < 8; nt++) {
                mx0 = fmaxf(mx0, fmaxf(sv[nt][0], sv[nt][1]));
                mx1 = fmaxf(mx1, fmaxf(sv[nt][2], sv[nt][3]));
            }
            mx0 = fmaxf(mx0, __shfl_xor_sync(0xffffffffu, mx0, 1));
            mx0 = fmaxf(mx0, __shfl_xor_sync(0xffffffffu, mx0, 2));
            mx1 = fmaxf(mx1, __shfl_xor_sync(0xffffffffu, mx1, 1));
            mx1 = fmaxf(mx1, __shfl_xor_sync(0xffffffffu, mx1, 2));

            const float mn0 = fmaxf(m0v, mx0), mn1 = fmaxf(m1v, mx1);
            const float al0 = __expf(m0v - mn0), al1 = __expf(m1v - mn1);
            m0v = mn0; m1v = mn1;

            float sum0 = 0.0f, sum1 = 0.0f;
            #pragma unroll
            for (int nt = 0; nt < 8; nt++) {
                sv[nt][0] = __expf(sv[nt][0] - mn0); sum0 += sv[nt][0];
                sv[nt][1] = __expf(sv[nt][1] - mn0); sum0 += sv[nt][1];
                sv[nt][2] = __expf(sv[nt][2] - mn1); sum1 += sv[nt][2];
                sv[nt][3] = __expf(sv[nt][3] - mn1); sum1 += sv[nt][3];
            }
            sum0 += __shfl_xor_sync(0xffffffffu, sum0, 1);
            sum0 += __shfl_xor_sync(0xffffffffu, sum0, 2);
            sum1 += __shfl_xor_sync(0xffffffffu, sum1, 1);
            sum1 += __shfl_xor_sync(0xffffffffu, sum1, 2);
            l0 = l0 * al0 + sum0;
            l1 = l1 * al1 + sum1;

            #pragma unroll
            for (int nt = 0; nt < 8; nt++) {
                o[nt][0] *= al0; o[nt][1] *= al0;
                o[nt][2] *= al1; o[nt][3] *= al1;
            }

            #pragma unroll
            for (int ks = 0; ks < 4; ks++) {
                const uint32_t p0 = packh2(sv[2 * ks][0],     sv[2 * ks][1]);
                const uint32_t p1 = packh2(sv[2 * ks][2],     sv[2 * ks][3]);
                const uint32_t p2 = packh2(sv[2 * ks + 1][0], sv[2 * ks + 1][1]);
                const uint32_t p3 = packh2(sv[2 * ks + 1][2], sv[2 * ks + 1][3]);
                #pragma unroll
                for (int p = 0; p < 4; p++) {
                    int srow = ks * 16 + vrl;
                    int ch = (2 * p + vck) ^ (srow & 7);
                    uint32_t r0, r1, r2, r3;
                    ldsm4t(r0, r1, r2, r3, Vb + srow * 128 + (ch << 4));
                    mma16(o[2 * p],     p0, p1, p2, p3, r0, r1);
                    mma16(o[2 * p + 1], p0, p1, p2, p3, r2, r3);
                }
            }
        }

        const float inv0 = 1.0f / l0, inv1 = 1.0f / l1;
        __half* dlo = g_atth + ((size_t)(q0 + w * 16 + g) * Bb + b) * Ee + h * Dh;
        __half* dhi = dlo + (size_t)8 * Bb * Ee;
        #pragma unroll
        for (int nt = 0; nt < 8; nt++) {
            const int c = nt * 8 + 2 * t;
            *(uint32_t*)&dlo[c] = packh2(o[nt][0] * inv0, o[nt][1] * inv0);
            *(uint32_t*)&dhi[c] = packh2(o[nt][2] * inv1, o[nt][3] * inv1);
        }

        // Publish completion (release)
        __threadfence();
        __syncthreads();
        if (tid == 0) atomicAdd(&g_cnt[qt], 1);
        return;
    }

    // ================= GEMM2 path =================
    {
        const int t2 = bid - NFLASH;            // 0..511, early tokens first
        const int m_tile = t2 >> 3;             // 0..63
        const int n_tile = t2 & 7;              // 0..7
        const int m0 = m_tile * BM;
        const int n0 = n_tile * BN;
        const int qw = m_tile >> 2;             // qt this row tile depends on

        // Spin until all 128 flash blocks of qt==qw have published (acquire)
        if (tid == 0) {
            int v;
            do {
                asm volatile("ld.acquire.gpu.global.s32 %0, [%1];"
                             : "=r"(v) : "l"(&g_cnt[qw]) : "memory");
                if (v < 128) __nanosleep(256);
            } while (v < 128);
        }
        __syncthreads();

        const __half* Ah = g_atth;
        const __half* Bh = g_w2h;
        const int wm = w & 1;
        const int wn = w >> 1;
        const int K = Ee, N = Ee;

        float acc[4][8][4];
        #pragma unroll
        for (int mt = 0; mt < 4; mt++)
            #pragma unroll
            for (int nt = 0; nt < 8; nt++)
                #pragma unroll
                for (int i = 0; i < 4; i++) acc[mt][nt][i] = 0.0f;

        auto load_stage = [&](int s, int c) {
            const uint32_t base = sb + s * STG;
            const int k0 = c * BKH;
            #pragma unroll
            for (int i = 0; i < 8; i++) {
                int q = tid + i * 128;
                uint32_t dst;
                const __half* src;
                if (q < 512) {
                    int r = q >> 2, ch = q & 3;
                    src = Ah + (size_t)(m0 + r) * K + k0 + ch * 8;
                    dst = base + r * 64 + ((ch ^ ((r >> 1) & 3)) << 4);
                } else {
                    int q2 = q - 512;
                    int r = q2 >> 2, ch = q2 & 3;
                    src = Bh + (size_t)(n0 + r) * K + k0 + ch * 8;
                    dst = base + ABY + r * 64 + ((ch ^ ((r >> 1) & 3)) << 4);
                }
                asm volatile("cp.async.cg.shared.global [%0], [%1], 16;" :: "r"(dst), "l"(src));
            }
            asm volatile("cp.async.commit_group;" ::: "memory");
        };

        const int nk = K / BKH;
        load_stage(0, 0);
        load_stage(1, 1);
        load_stage(2, 2);

        const int a_rl = ((lane >> 3) & 1) * 8 + (lane & 7);
        const int a_ck = lane >> 4;
        const int b_rl = ((lane >> 4) & 1) * 8 + (lane & 7);
        const int b_ck = (lane >> 3) & 1;

        uint32_t aoff[2][4], boff[2][4];
        #pragma unroll
        for (int ks = 0; ks < 2; ks++) {
            #pragma unroll
            for (int mt = 0; mt < 4; mt++) {
                int ar = wm * 64 + mt * 16 + a_rl;
                int ch = (2 * ks + a_ck) ^ ((ar >> 1) & 3);
                aoff[ks][mt] = ar * 64 + (ch << 4);
            }
            #pragma unroll
            for (int p = 0; p < 4; p++) {
                int br = wn * 64 + p * 16 + b_rl;
                int ch = (2 * ks + b_ck) ^ ((br >> 1) & 3);
                boff[ks][p] = ABY + br * 64 + (ch << 4);
            }
        }

        for (int c = 0; c < nk; c++) {
            const int s = c & (NSG - 1);
            if (c < nk - 1) asm volatile("cp.async.wait_group 2;" ::: "memory");
            else            asm volatile("cp.async.wait_group 0;" ::: "memory");
            __syncthreads();
            if (c + NSG - 1 < nk) load_stage((c + NSG - 1) & (NSG - 1), c + NSG - 1);

            const uint32_t base = sb + s * STG;
            #pragma unroll
            for (int ks = 0; ks < 2; ks++) {
                uint32_t af[4][4], bf[8][2];
                #pragma unroll
                for (int mt = 0; mt < 4; mt++)
                    ldsm4(af[mt][0], af[mt][1], af[mt][2], af[mt][3], base + aoff[ks][mt]);
                #pragma unroll
                for (int p = 0; p < 4; p++) {
                    uint32_t r0, r1, r2, r3;
                    ldsm4(r0, r1, r2, r3, base + boff[ks][p]);
                    bf[2 * p][0] = r0;     bf[2 * p][1] = r1;
                    bf[2 * p + 1][0] = r2; bf[2 * p + 1][1] = r3;
                }
                #pragma unroll
                for (int mt = 0; mt < 4; mt++)
                    #pragma unroll
                    for (int nt = 0; nt < 8; nt++)
                        mma16(acc[mt][nt], af[mt][0], af[mt][1], af[mt][2], af[mt][3],
                              bf[nt][0], bf[nt][1]);
            }
        }

        const int g2 = lane >> 2, t3 = lane & 3;
        #pragma unroll
        for (int mt = 0; mt < 4; mt++) {
            const int r0 = m0 + wm * 64 + mt * 16 + g2;
            #pragma unroll
            for (int nt = 0; nt < 8; nt++) {
                const int col = n0 + wn * 64 + nt * 8 + 2 * t3;
                const float b0 = out_b[col], b1 = out_b[col + 1];
                *(float2*)&out[(size_t)r0 * N + col] =
                    make_float2(acc[mt][nt][0] + b0, acc[mt][nt][1] + b1);
                *(float2*)&out[(size_t)(r0 + 8) * N + col] =
                    make_float2(acc[mt][nt][2] + b0, acc[mt][nt][3] + b1);
            }
        }
    }
}

// ---------------------------------------------------------------------------
// Launch
// ---------------------------------------------------------------------------
extern "C" void kernel_launch(void* const* d_in, const int* in_sizes, int n_in,
                              void* d_out, int out_size)
{
    const float* query = (const float*)d_in[0];
    const float* qkv_w = (const float*)d_in[1];
    const float* qkv_b = (const float*)d_in[2];
    const float* out_w = (const float*)d_in[3];
    const float* out_b = (const float*)d_in[4];
    float* out = (float*)d_out;

    void *p_xh = nullptr, *p_w1h = nullptr, *p_w2h = nullptr, *p_qkvh = nullptr;
    cudaGetSymbolAddress(&p_xh,   g_xh);
    cudaGetSymbolAddress(&p_w1h,  g_w1h);
    cudaGetSymbolAddress(&p_w2h,  g_w2h);
    cudaGetSymbolAddress(&p_qkvh, g_qkvh);

    cudaFuncSetAttribute(gemm_f16,    cudaFuncAttributeMaxDynamicSharedMemorySize, GSM);
    cudaFuncSetAttribute(flash_gemm2, cudaFuncAttributeMaxDynamicSharedMemorySize, GSM);

    // 0) fused prepass: fp32->fp16 conversions + counter resets
    const int ntot4 = NQ4 + NW14 + NW24;
    prepass<<<(ntot4 + 255) / 256, 256>>>(
        (const float4*)query, (const float4*)qkv_w, (const float4*)out_w,
        (uint2*)p_xh, (uint2*)p_w1h, (uint2*)p_w2h);

    // 1) QKV projection -> fp16, Q block scaled by 0.125 (proven R7 GEMM)
    gemm_f16<<<dim3(QKVF / BN, MROWS / BM), 128, GSM>>>(
        (const __half*)p_xh, (const __half*)p_w1h, qkv_b,
        (__half*)p_qkvh, MROWS, QKVF, Ee, 1);

    // 2+3) Fused causal flash attention + output projection
    flash_gemm2<<<NFLASH + (MROWS / BM) * (Ee / BN), 128, GSM>>>(out_b, out);
}